// round 11
// baseline (speedup 1.0000x reference)
#include <cuda_runtime.h>
#include <stdint.h>

// Output nodes = N_NODES / 3 = 1,000,000
#define MAX_OUT_NODES 1000000
__device__ float g_agg[MAX_OUT_NODES];   // static zero-init; finalize re-zeros it
                                         // each call, so scatter always starts
                                         // from zeros (graph-replay invariant).

// ---------------------------------------------------------------------------
// Kernel 1: edge scatter, 8 edges per thread, TPB=512 (final probe; body is
// the best measured 8-edge config).
// Only edges with dst % 3 == 0 contribute (the output subsamples h at stride
// 3 before the MLP) -> skip the x gather + atomic for 2/3 of edges.
//
// At the L1tex/LSU lane-op hardware floor:
//   16M divergent gather wavefronts (~1.0 cyc/wf)
// + 16M spread-address REDG lanes   (~1.29 cyc/lane)
// = ~247K cyc/SM over 148 SMs ~ 128 us @ NAT clock. Measured ~129.5 us.
// Rejected with measurements: 4/16-edge unrolls, 3-way splits, __ldcs,
// PDL overlap, compaction/binning (theory).
// ---------------------------------------------------------------------------
__global__ void scatter_kernel(const int* __restrict__ src,
                               const int* __restrict__ dst,
                               const float* __restrict__ x,
                               int nedges) {
    const int4* src4 = reinterpret_cast<const int4*>(src);
    const int4* dst4 = reinterpret_cast<const int4*>(dst);
    int t = blockIdx.x * blockDim.x + threadIdx.x;   // octet index (8 edges)
    int noct = nedges >> 3;

    if (t < noct) {
        int4 da = __ldg(&dst4[2 * t]);
        int4 db = __ldg(&dst4[2 * t + 1]);
        int4 sa = __ldg(&src4[2 * t]);
        int4 sb = __ldg(&src4[2 * t + 1]);

        int d[8] = {da.x, da.y, da.z, da.w, db.x, db.y, db.z, db.w};
        int s[8] = {sa.x, sa.y, sa.z, sa.w, sb.x, sb.y, sb.z, sb.w};

        bool  ok[8];
        float v[8];
#pragma unroll
        for (int k = 0; k < 8; k++) {
            ok[k] = (d[k] % 3 == 0);
        }
#pragma unroll
        for (int k = 0; k < 8; k++) {
            v[k] = ok[k] ? __ldg(&x[s[k]]) : 0.0f;
        }
#pragma unroll
        for (int k = 0; k < 8; k++) {
            if (ok[k]) atomicAdd(&g_agg[d[k] / 3], v[k]);
        }
    }

    // Tail (nedges not a multiple of 8)
    int tail_start = noct << 3;
    int e = tail_start + t;
    if (t < 8 && e < nedges) {
        int dd = __ldg(&dst[e]);
        if (dd % 3 == 0) {
            int ss = __ldg(&src[e]);
            atomicAdd(&g_agg[dd / 3], __ldg(&x[ss]));
        }
    }
}

// ---------------------------------------------------------------------------
// Kernel 2: finalize, 8 outputs per thread (2 float4 quads), all loads
// issued before any consumption (latency-bound -> maximize MLP).
// TPB=128 -> 977 blocks for smooth wave balance across 148 SMs.
// h = agg*Wl + x[3i]*Wr, then MLP(1->2->relu->1). Also resets g_agg.
// ---------------------------------------------------------------------------
__device__ __forceinline__ float4 mlp4(float4 a, float x0, float x1, float x2,
                                       float x3, float wl, float wr,
                                       float w10, float w11, float bb0,
                                       float bb1, float w20, float w21,
                                       float bb2) {
    float h0 = fmaf(a.x, wl, x0 * wr);
    float h1 = fmaf(a.y, wl, x1 * wr);
    float h2 = fmaf(a.z, wl, x2 * wr);
    float h3 = fmaf(a.w, wl, x3 * wr);
    float4 o;
    o.x = fmaf(fmaxf(fmaf(h0, w10, bb0), 0.f), w20,
               fmaf(fmaxf(fmaf(h0, w11, bb1), 0.f), w21, bb2));
    o.y = fmaf(fmaxf(fmaf(h1, w10, bb0), 0.f), w20,
               fmaf(fmaxf(fmaf(h1, w11, bb1), 0.f), w21, bb2));
    o.z = fmaf(fmaxf(fmaf(h2, w10, bb0), 0.f), w20,
               fmaf(fmaxf(fmaf(h2, w11, bb1), 0.f), w21, bb2));
    o.w = fmaf(fmaxf(fmaf(h3, w10, bb0), 0.f), w20,
               fmaf(fmaxf(fmaf(h3, w11, bb1), 0.f), w21, bb2));
    return o;
}

__global__ void finalize_kernel(const float* __restrict__ x,
                                const float* __restrict__ Wl,
                                const float* __restrict__ Wr,
                                const float* __restrict__ W1,
                                const float* __restrict__ b1,
                                const float* __restrict__ W2,
                                const float* __restrict__ b2,
                                float* __restrict__ out,
                                int m8) {       // m/8 octets
    int t = blockIdx.x * blockDim.x + threadIdx.x;
    if (t >= m8) return;

    float4* agg4 = reinterpret_cast<float4*>(g_agg);
    const float4* x4 = reinterpret_cast<const float4*>(x);
    float4* out4 = reinterpret_cast<float4*>(out);

    int q0 = 2 * t;
    int q1 = 2 * t + 1;

    // ---- issue ALL loads up front (8 independent LDG.128) ----
    float4 a0 = agg4[q0];
    float4 a1 = agg4[q1];
    float4 xa0 = __ldg(&x4[3 * q0]);
    float4 xb0 = __ldg(&x4[3 * q0 + 1]);
    float4 xc0 = __ldg(&x4[3 * q0 + 2]);
    float4 xa1 = __ldg(&x4[3 * q1]);
    float4 xb1 = __ldg(&x4[3 * q1 + 1]);
    float4 xc1 = __ldg(&x4[3 * q1 + 2]);

    // reset agg for next call/replay
    float4 z = make_float4(0.f, 0.f, 0.f, 0.f);
    agg4[q0] = z;
    agg4[q1] = z;

    float wl = __ldg(&Wl[0]);
    float wr = __ldg(&Wr[0]);
    float w10 = __ldg(&W1[0]), w11 = __ldg(&W1[1]);
    float bb0 = __ldg(&b1[0]), bb1 = __ldg(&b1[1]);
    float w20 = __ldg(&W2[0]), w21 = __ldg(&W2[1]);
    float bb2 = __ldg(&b2[0]);

    // quad 0 roots: x[12q0], x[12q0+3], x[12q0+6], x[12q0+9]
    out4[q0] = mlp4(a0, xa0.x, xa0.w, xb0.z, xc0.y,
                    wl, wr, w10, w11, bb0, bb1, w20, w21, bb2);
    out4[q1] = mlp4(a1, xa1.x, xa1.w, xb1.z, xc1.y,
                    wl, wr, w10, w11, bb0, bb1, w20, w21, bb2);
}

// ---------------------------------------------------------------------------
// Launch
// Inputs (metadata order): x[N,1] f32, edge_index[2,E] int32 (downcast from
// int64), W_l[1,1], W_r[1,1], W1[2,1], b1[2], W2[1,2], b2[1]
// Output: float[N/3]; out_size = 1,000,000 (divisible by 8).
// ---------------------------------------------------------------------------
extern "C" void kernel_launch(void* const* d_in, const int* in_sizes, int n_in,
                              void* d_out, int out_size) {
    const float* x  = (const float*)d_in[0];
    const int* edge_index = (const int*)d_in[1];
    const float* Wl = (const float*)d_in[2];
    const float* Wr = (const float*)d_in[3];
    const float* W1 = (const float*)d_in[4];
    const float* b1 = (const float*)d_in[5];
    const float* W2 = (const float*)d_in[6];
    const float* b2 = (const float*)d_in[7];
    float* out = (float*)d_out;

    int nedges = in_sizes[1] / 2;   // E (edge_index has 2*E elements)
    int m = out_size;               // N/3 output nodes
    int m8 = m / 8;

    const int* src = edge_index;
    const int* dst = edge_index + nedges;

    // 1) scatter: one thread per 8 edges, TPB=512 (this round's probe)
    int noct = nedges >> 3;
    int blocks = (noct + 511) / 512;
    scatter_kernel<<<blocks, 512>>>(src, dst, x, nedges);

    // 2) finalize: one thread per 8 outputs, TPB=128 for wave balance
    finalize_kernel<<<(m8 + 127) / 128, 128>>>(x, Wl, Wr, W1, b1, W2, b2, out, m8);
}

// round 12
// speedup vs baseline: 1.0099x; 1.0099x over previous
#include <cuda_runtime.h>
#include <stdint.h>

// Output nodes = N_NODES / 3 = 1,000,000
#define MAX_OUT_NODES 1000000
__device__ float g_agg[MAX_OUT_NODES];   // static zero-init; finalize re-zeros it
                                         // each call, so scatter always starts
                                         // from zeros (graph-replay invariant).

// ---------------------------------------------------------------------------
// Kernel 1: edge scatter, 8 edges per thread, TPB=256 (best measured).
// Only edges with dst % 3 == 0 contribute (the output subsamples h at stride
// 3 before the MLP) -> skip the x gather + atomic for 2/3 of edges.
//
// At the L1tex/LSU lane-op hardware floor:
//   16M divergent gather wavefronts (~1.0 cyc/wf)
// + 16M spread-address REDG lanes   (~1.29 cyc/lane)
// = ~247K cyc/SM over 148 SMs ~ 128 us @ NAT clock. Measured ~129.5 us.
// Swept and rejected with measurements: 4/16-edge unrolls, TPB=512,
// 3-way launch splits, __ldcs streaming, PDL overlap; compaction/smem
// binning/warp dedupe rejected on quantitative theory.
// ---------------------------------------------------------------------------
__global__ void scatter_kernel(const int* __restrict__ src,
                               const int* __restrict__ dst,
                               const float* __restrict__ x,
                               int nedges) {
    const int4* src4 = reinterpret_cast<const int4*>(src);
    const int4* dst4 = reinterpret_cast<const int4*>(dst);
    int t = blockIdx.x * blockDim.x + threadIdx.x;   // octet index (8 edges)
    int noct = nedges >> 3;

    if (t < noct) {
        int4 da = __ldg(&dst4[2 * t]);
        int4 db = __ldg(&dst4[2 * t + 1]);
        int4 sa = __ldg(&src4[2 * t]);
        int4 sb = __ldg(&src4[2 * t + 1]);

        int d[8] = {da.x, da.y, da.z, da.w, db.x, db.y, db.z, db.w};
        int s[8] = {sa.x, sa.y, sa.z, sa.w, sb.x, sb.y, sb.z, sb.w};

        bool  ok[8];
        float v[8];
#pragma unroll
        for (int k = 0; k < 8; k++) {
            ok[k] = (d[k] % 3 == 0);
        }
#pragma unroll
        for (int k = 0; k < 8; k++) {
            v[k] = ok[k] ? __ldg(&x[s[k]]) : 0.0f;
        }
#pragma unroll
        for (int k = 0; k < 8; k++) {
            if (ok[k]) atomicAdd(&g_agg[d[k] / 3], v[k]);
        }
    }

    // Tail (nedges not a multiple of 8)
    int tail_start = noct << 3;
    int e = tail_start + t;
    if (t < 8 && e < nedges) {
        int dd = __ldg(&dst[e]);
        if (dd % 3 == 0) {
            int ss = __ldg(&src[e]);
            atomicAdd(&g_agg[dd / 3], __ldg(&x[ss]));
        }
    }
}

// ---------------------------------------------------------------------------
// Kernel 2: finalize, 8 outputs per thread (2 float4 quads), all loads
// issued before any consumption (latency-bound -> maximize MLP).
// TPB=128 -> 977 blocks for smooth wave balance across 148 SMs.
// h = agg*Wl + x[3i]*Wr, then MLP(1->2->relu->1). Also resets g_agg.
// ---------------------------------------------------------------------------
__device__ __forceinline__ float4 mlp4(float4 a, float x0, float x1, float x2,
                                       float x3, float wl, float wr,
                                       float w10, float w11, float bb0,
                                       float bb1, float w20, float w21,
                                       float bb2) {
    float h0 = fmaf(a.x, wl, x0 * wr);
    float h1 = fmaf(a.y, wl, x1 * wr);
    float h2 = fmaf(a.z, wl, x2 * wr);
    float h3 = fmaf(a.w, wl, x3 * wr);
    float4 o;
    o.x = fmaf(fmaxf(fmaf(h0, w10, bb0), 0.f), w20,
               fmaf(fmaxf(fmaf(h0, w11, bb1), 0.f), w21, bb2));
    o.y = fmaf(fmaxf(fmaf(h1, w10, bb0), 0.f), w20,
               fmaf(fmaxf(fmaf(h1, w11, bb1), 0.f), w21, bb2));
    o.z = fmaf(fmaxf(fmaf(h2, w10, bb0), 0.f), w20,
               fmaf(fmaxf(fmaf(h2, w11, bb1), 0.f), w21, bb2));
    o.w = fmaf(fmaxf(fmaf(h3, w10, bb0), 0.f), w20,
               fmaf(fmaxf(fmaf(h3, w11, bb1), 0.f), w21, bb2));
    return o;
}

__global__ void finalize_kernel(const float* __restrict__ x,
                                const float* __restrict__ Wl,
                                const float* __restrict__ Wr,
                                const float* __restrict__ W1,
                                const float* __restrict__ b1,
                                const float* __restrict__ W2,
                                const float* __restrict__ b2,
                                float* __restrict__ out,
                                int m8) {       // m/8 octets
    int t = blockIdx.x * blockDim.x + threadIdx.x;
    if (t >= m8) return;

    float4* agg4 = reinterpret_cast<float4*>(g_agg);
    const float4* x4 = reinterpret_cast<const float4*>(x);
    float4* out4 = reinterpret_cast<float4*>(out);

    int q0 = 2 * t;
    int q1 = 2 * t + 1;

    // ---- issue ALL loads up front (8 independent LDG.128) ----
    float4 a0 = agg4[q0];
    float4 a1 = agg4[q1];
    float4 xa0 = __ldg(&x4[3 * q0]);
    float4 xb0 = __ldg(&x4[3 * q0 + 1]);
    float4 xc0 = __ldg(&x4[3 * q0 + 2]);
    float4 xa1 = __ldg(&x4[3 * q1]);
    float4 xb1 = __ldg(&x4[3 * q1 + 1]);
    float4 xc1 = __ldg(&x4[3 * q1 + 2]);

    // reset agg for next call/replay
    float4 z = make_float4(0.f, 0.f, 0.f, 0.f);
    agg4[q0] = z;
    agg4[q1] = z;

    float wl = __ldg(&Wl[0]);
    float wr = __ldg(&Wr[0]);
    float w10 = __ldg(&W1[0]), w11 = __ldg(&W1[1]);
    float bb0 = __ldg(&b1[0]), bb1 = __ldg(&b1[1]);
    float w20 = __ldg(&W2[0]), w21 = __ldg(&W2[1]);
    float bb2 = __ldg(&b2[0]);

    // quad 0 roots: x[12q0], x[12q0+3], x[12q0+6], x[12q0+9]
    out4[q0] = mlp4(a0, xa0.x, xa0.w, xb0.z, xc0.y,
                    wl, wr, w10, w11, bb0, bb1, w20, w21, bb2);
    out4[q1] = mlp4(a1, xa1.x, xa1.w, xb1.z, xc1.y,
                    wl, wr, w10, w11, bb0, bb1, w20, w21, bb2);
}

// ---------------------------------------------------------------------------
// Launch
// Inputs (metadata order): x[N,1] f32, edge_index[2,E] int32 (downcast from
// int64), W_l[1,1], W_r[1,1], W1[2,1], b1[2], W2[1,2], b2[1]
// Output: float[N/3]; out_size = 1,000,000 (divisible by 8).
// ---------------------------------------------------------------------------
extern "C" void kernel_launch(void* const* d_in, const int* in_sizes, int n_in,
                              void* d_out, int out_size) {
    const float* x  = (const float*)d_in[0];
    const int* edge_index = (const int*)d_in[1];
    const float* Wl = (const float*)d_in[2];
    const float* Wr = (const float*)d_in[3];
    const float* W1 = (const float*)d_in[4];
    const float* b1 = (const float*)d_in[5];
    const float* W2 = (const float*)d_in[6];
    const float* b2 = (const float*)d_in[7];
    float* out = (float*)d_out;

    int nedges = in_sizes[1] / 2;   // E (edge_index has 2*E elements)
    int m = out_size;               // N/3 output nodes
    int m8 = m / 8;

    const int* src = edge_index;
    const int* dst = edge_index + nedges;

    // 1) scatter: one thread per 8 edges, TPB=256 (best measured)
    int noct = nedges >> 3;
    int blocks = (noct + 255) / 256;
    scatter_kernel<<<blocks, 256>>>(src, dst, x, nedges);

    // 2) finalize: one thread per 8 outputs, TPB=128 for wave balance
    finalize_kernel<<<(m8 + 127) / 128, 128>>>(x, Wl, Wr, W1, b1, W2, b2, out, m8);
}

// round 13
// speedup vs baseline: 1.0177x; 1.0077x over previous
#include <cuda_runtime.h>
#include <stdint.h>

// Output nodes = N_NODES / 3 = 1,000,000
#define MAX_OUT_NODES 1000000
__device__ float g_agg[MAX_OUT_NODES];   // static zero-init; finalize re-zeros it
                                         // each call, so scatter always starts
                                         // from zeros (graph-replay invariant).

// ---------------------------------------------------------------------------
// Kernel 1: edge scatter, 8 edges per thread, TPB=256 (best measured).
// Only edges with dst % 3 == 0 contribute (the output subsamples h at stride
// 3 before the MLP) -> skip the x gather + atomic for 2/3 of edges.
//
// FINAL — at the L1tex/LSU lane-op hardware floor:
//   16M divergent gather wavefronts (~1.0 cyc/wf)
// + 16M spread-address REDG lanes   (~1.29 cyc/lane)
// = ~247K cyc/SM over 148 SMs ~ 128 us @ NAT clock. Measured ~129.5 us (99%).
// Swept & rejected with measurements: 4/16-edge unrolls, TPB=512, 3-way
// launch splits, __ldcs streaming, PDL overlap. Rejected on quantitative
// theory: compaction (+traffic, same lanes), smem binning (4MB agg >> 228KB
// L1), warp dst-dedupe (collision p~0.4%), v2 vector RED (random dsts).
// ---------------------------------------------------------------------------
__global__ void scatter_kernel(const int* __restrict__ src,
                               const int* __restrict__ dst,
                               const float* __restrict__ x,
                               int nedges) {
    const int4* src4 = reinterpret_cast<const int4*>(src);
    const int4* dst4 = reinterpret_cast<const int4*>(dst);
    int t = blockIdx.x * blockDim.x + threadIdx.x;   // octet index (8 edges)
    int noct = nedges >> 3;

    if (t < noct) {
        int4 da = __ldg(&dst4[2 * t]);
        int4 db = __ldg(&dst4[2 * t + 1]);
        int4 sa = __ldg(&src4[2 * t]);
        int4 sb = __ldg(&src4[2 * t + 1]);

        int d[8] = {da.x, da.y, da.z, da.w, db.x, db.y, db.z, db.w};
        int s[8] = {sa.x, sa.y, sa.z, sa.w, sb.x, sb.y, sb.z, sb.w};

        bool  ok[8];
        float v[8];
#pragma unroll
        for (int k = 0; k < 8; k++) {
            ok[k] = (d[k] % 3 == 0);
        }
#pragma unroll
        for (int k = 0; k < 8; k++) {
            v[k] = ok[k] ? __ldg(&x[s[k]]) : 0.0f;
        }
#pragma unroll
        for (int k = 0; k < 8; k++) {
            if (ok[k]) atomicAdd(&g_agg[d[k] / 3], v[k]);
        }
    }

    // Tail (nedges not a multiple of 8; E=48M is, but keep it general)
    int tail_start = noct << 3;
    int e = tail_start + t;
    if (t < 8 && e < nedges) {
        int dd = __ldg(&dst[e]);
        if (dd % 3 == 0) {
            int ss = __ldg(&src[e]);
            atomicAdd(&g_agg[dd / 3], __ldg(&x[ss]));
        }
    }
}

// ---------------------------------------------------------------------------
// Kernel 2: finalize, 8 outputs per thread (2 float4 quads), all loads
// issued before any consumption (latency-bound -> maximize MLP).
// TPB=128 -> 977 blocks for smooth wave balance across 148 SMs.
// h = agg*Wl + x[3i]*Wr, then MLP(1->2->relu->1). Also resets g_agg.
// ---------------------------------------------------------------------------
__device__ __forceinline__ float4 mlp4(float4 a, float x0, float x1, float x2,
                                       float x3, float wl, float wr,
                                       float w10, float w11, float bb0,
                                       float bb1, float w20, float w21,
                                       float bb2) {
    float h0 = fmaf(a.x, wl, x0 * wr);
    float h1 = fmaf(a.y, wl, x1 * wr);
    float h2 = fmaf(a.z, wl, x2 * wr);
    float h3 = fmaf(a.w, wl, x3 * wr);
    float4 o;
    o.x = fmaf(fmaxf(fmaf(h0, w10, bb0), 0.f), w20,
               fmaf(fmaxf(fmaf(h0, w11, bb1), 0.f), w21, bb2));
    o.y = fmaf(fmaxf(fmaf(h1, w10, bb0), 0.f), w20,
               fmaf(fmaxf(fmaf(h1, w11, bb1), 0.f), w21, bb2));
    o.z = fmaf(fmaxf(fmaf(h2, w10, bb0), 0.f), w20,
               fmaf(fmaxf(fmaf(h2, w11, bb1), 0.f), w21, bb2));
    o.w = fmaf(fmaxf(fmaf(h3, w10, bb0), 0.f), w20,
               fmaf(fmaxf(fmaf(h3, w11, bb1), 0.f), w21, bb2));
    return o;
}

__global__ void finalize_kernel(const float* __restrict__ x,
                                const float* __restrict__ Wl,
                                const float* __restrict__ Wr,
                                const float* __restrict__ W1,
                                const float* __restrict__ b1,
                                const float* __restrict__ W2,
                                const float* __restrict__ b2,
                                float* __restrict__ out,
                                int m8) {       // m/8 octets
    int t = blockIdx.x * blockDim.x + threadIdx.x;
    if (t >= m8) return;

    float4* agg4 = reinterpret_cast<float4*>(g_agg);
    const float4* x4 = reinterpret_cast<const float4*>(x);
    float4* out4 = reinterpret_cast<float4*>(out);

    int q0 = 2 * t;
    int q1 = 2 * t + 1;

    // ---- issue ALL loads up front (8 independent LDG.128) ----
    float4 a0 = agg4[q0];
    float4 a1 = agg4[q1];
    float4 xa0 = __ldg(&x4[3 * q0]);
    float4 xb0 = __ldg(&x4[3 * q0 + 1]);
    float4 xc0 = __ldg(&x4[3 * q0 + 2]);
    float4 xa1 = __ldg(&x4[3 * q1]);
    float4 xb1 = __ldg(&x4[3 * q1 + 1]);
    float4 xc1 = __ldg(&x4[3 * q1 + 2]);

    // reset agg for next call/replay
    float4 z = make_float4(0.f, 0.f, 0.f, 0.f);
    agg4[q0] = z;
    agg4[q1] = z;

    float wl = __ldg(&Wl[0]);
    float wr = __ldg(&Wr[0]);
    float w10 = __ldg(&W1[0]), w11 = __ldg(&W1[1]);
    float bb0 = __ldg(&b1[0]), bb1 = __ldg(&b1[1]);
    float w20 = __ldg(&W2[0]), w21 = __ldg(&W2[1]);
    float bb2 = __ldg(&b2[0]);

    // quad 0 roots: x[12q0], x[12q0+3], x[12q0+6], x[12q0+9]
    out4[q0] = mlp4(a0, xa0.x, xa0.w, xb0.z, xc0.y,
                    wl, wr, w10, w11, bb0, bb1, w20, w21, bb2);
    out4[q1] = mlp4(a1, xa1.x, xa1.w, xb1.z, xc1.y,
                    wl, wr, w10, w11, bb0, bb1, w20, w21, bb2);
}

// ---------------------------------------------------------------------------
// Launch
// Inputs (metadata order): x[N,1] f32, edge_index[2,E] int32 (downcast from
// int64), W_l[1,1], W_r[1,1], W1[2,1], b1[2], W2[1,2], b2[1]
// Output: float[N/3]; out_size = 1,000,000 (divisible by 8).
// ---------------------------------------------------------------------------
extern "C" void kernel_launch(void* const* d_in, const int* in_sizes, int n_in,
                              void* d_out, int out_size) {
    const float* x  = (const float*)d_in[0];
    const int* edge_index = (const int*)d_in[1];
    const float* Wl = (const float*)d_in[2];
    const float* Wr = (const float*)d_in[3];
    const float* W1 = (const float*)d_in[4];
    const float* b1 = (const float*)d_in[5];
    const float* W2 = (const float*)d_in[6];
    const float* b2 = (const float*)d_in[7];
    float* out = (float*)d_out;

    int nedges = in_sizes[1] / 2;   // E (edge_index has 2*E elements)
    int m = out_size;               // N/3 output nodes
    int m8 = m / 8;

    const int* src = edge_index;
    const int* dst = edge_index + nedges;

    // 1) scatter: one thread per 8 edges, TPB=256 (best measured)
    int noct = nedges >> 3;
    int blocks = (noct + 255) / 256;
    scatter_kernel<<<blocks, 256>>>(src, dst, x, nedges);

    // 2) finalize: one thread per 8 outputs, TPB=128 for wave balance
    finalize_kernel<<<(m8 + 127) / 128, 128>>>(x, Wl, Wr, W1, b1, W2, b2, out, m8);
}

// round 14
// speedup vs baseline: 1.0194x; 1.0016x over previous
#include <cuda_runtime.h>
#include <stdint.h>

// Output nodes = N_NODES / 3 = 1,000,000
#define MAX_OUT_NODES 1000000
__device__ float g_agg[MAX_OUT_NODES];   // static zero-init; finalize re-zeros it
                                         // each call, so scatter always starts
                                         // from zeros (graph-replay invariant).

// ---------------------------------------------------------------------------
// Kernel 1: edge scatter, 8 edges per thread, TPB=256 (best measured).
// Only edges with dst % 3 == 0 contribute (the output subsamples h at stride
// 3 before the MLP) -> skip the x gather + atomic for 2/3 of edges.
//
// FINAL — at the L1tex/LSU lane-op hardware floor:
//   16M divergent gather wavefronts (~1.0 cyc/wf)
// + 16M spread-address REDG lanes   (~1.29 cyc/lane)
// = ~247K cyc/SM over 148 SMs ~ 128 us @ NAT clock. Measured ~129.4 us (99%).
// Swept & rejected with measurements: 4/16-edge unrolls, TPB=512, 3-way
// launch splits, __ldcs streaming, PDL overlap. Rejected on quantitative
// theory: compaction (+traffic, same lanes), smem binning (4MB agg >> 228KB
// L1), warp dst-dedupe (collision p~0.4%), v2 vector RED (random dsts),
// bf16 accumulation (rel-err budget).
// ---------------------------------------------------------------------------
__global__ void scatter_kernel(const int* __restrict__ src,
                               const int* __restrict__ dst,
                               const float* __restrict__ x,
                               int nedges) {
    const int4* src4 = reinterpret_cast<const int4*>(src);
    const int4* dst4 = reinterpret_cast<const int4*>(dst);
    int t = blockIdx.x * blockDim.x + threadIdx.x;   // octet index (8 edges)
    int noct = nedges >> 3;

    if (t < noct) {
        int4 da = __ldg(&dst4[2 * t]);
        int4 db = __ldg(&dst4[2 * t + 1]);
        int4 sa = __ldg(&src4[2 * t]);
        int4 sb = __ldg(&src4[2 * t + 1]);

        int d[8] = {da.x, da.y, da.z, da.w, db.x, db.y, db.z, db.w};
        int s[8] = {sa.x, sa.y, sa.z, sa.w, sb.x, sb.y, sb.z, sb.w};

        bool  ok[8];
        float v[8];
#pragma unroll
        for (int k = 0; k < 8; k++) {
            ok[k] = (d[k] % 3 == 0);
        }
#pragma unroll
        for (int k = 0; k < 8; k++) {
            v[k] = ok[k] ? __ldg(&x[s[k]]) : 0.0f;
        }
#pragma unroll
        for (int k = 0; k < 8; k++) {
            if (ok[k]) atomicAdd(&g_agg[d[k] / 3], v[k]);
        }
    }

    // Tail (nedges not a multiple of 8; E=48M is, but keep it general)
    int tail_start = noct << 3;
    int e = tail_start + t;
    if (t < 8 && e < nedges) {
        int dd = __ldg(&dst[e]);
        if (dd % 3 == 0) {
            int ss = __ldg(&src[e]);
            atomicAdd(&g_agg[dd / 3], __ldg(&x[ss]));
        }
    }
}

// ---------------------------------------------------------------------------
// Kernel 2: finalize, 8 outputs per thread (2 float4 quads), all loads
// issued before any consumption (latency-bound -> maximize MLP).
// TPB=128 -> 977 blocks for smooth wave balance across 148 SMs.
// h = agg*Wl + x[3i]*Wr, then MLP(1->2->relu->1). Also resets g_agg.
// ---------------------------------------------------------------------------
__device__ __forceinline__ float4 mlp4(float4 a, float x0, float x1, float x2,
                                       float x3, float wl, float wr,
                                       float w10, float w11, float bb0,
                                       float bb1, float w20, float w21,
                                       float bb2) {
    float h0 = fmaf(a.x, wl, x0 * wr);
    float h1 = fmaf(a.y, wl, x1 * wr);
    float h2 = fmaf(a.z, wl, x2 * wr);
    float h3 = fmaf(a.w, wl, x3 * wr);
    float4 o;
    o.x = fmaf(fmaxf(fmaf(h0, w10, bb0), 0.f), w20,
               fmaf(fmaxf(fmaf(h0, w11, bb1), 0.f), w21, bb2));
    o.y = fmaf(fmaxf(fmaf(h1, w10, bb0), 0.f), w20,
               fmaf(fmaxf(fmaf(h1, w11, bb1), 0.f), w21, bb2));
    o.z = fmaf(fmaxf(fmaf(h2, w10, bb0), 0.f), w20,
               fmaf(fmaxf(fmaf(h2, w11, bb1), 0.f), w21, bb2));
    o.w = fmaf(fmaxf(fmaf(h3, w10, bb0), 0.f), w20,
               fmaf(fmaxf(fmaf(h3, w11, bb1), 0.f), w21, bb2));
    return o;
}

__global__ void finalize_kernel(const float* __restrict__ x,
                                const float* __restrict__ Wl,
                                const float* __restrict__ Wr,
                                const float* __restrict__ W1,
                                const float* __restrict__ b1,
                                const float* __restrict__ W2,
                                const float* __restrict__ b2,
                                float* __restrict__ out,
                                int m8) {       // m/8 octets
    int t = blockIdx.x * blockDim.x + threadIdx.x;
    if (t >= m8) return;

    float4* agg4 = reinterpret_cast<float4*>(g_agg);
    const float4* x4 = reinterpret_cast<const float4*>(x);
    float4* out4 = reinterpret_cast<float4*>(out);

    int q0 = 2 * t;
    int q1 = 2 * t + 1;

    // ---- issue ALL loads up front (8 independent LDG.128) ----
    float4 a0 = agg4[q0];
    float4 a1 = agg4[q1];
    float4 xa0 = __ldg(&x4[3 * q0]);
    float4 xb0 = __ldg(&x4[3 * q0 + 1]);
    float4 xc0 = __ldg(&x4[3 * q0 + 2]);
    float4 xa1 = __ldg(&x4[3 * q1]);
    float4 xb1 = __ldg(&x4[3 * q1 + 1]);
    float4 xc1 = __ldg(&x4[3 * q1 + 2]);

    // reset agg for next call/replay
    float4 z = make_float4(0.f, 0.f, 0.f, 0.f);
    agg4[q0] = z;
    agg4[q1] = z;

    float wl = __ldg(&Wl[0]);
    float wr = __ldg(&Wr[0]);
    float w10 = __ldg(&W1[0]), w11 = __ldg(&W1[1]);
    float bb0 = __ldg(&b1[0]), bb1 = __ldg(&b1[1]);
    float w20 = __ldg(&W2[0]), w21 = __ldg(&W2[1]);
    float bb2 = __ldg(&b2[0]);

    // quad 0 roots: x[12q0], x[12q0+3], x[12q0+6], x[12q0+9]
    out4[q0] = mlp4(a0, xa0.x, xa0.w, xb0.z, xc0.y,
                    wl, wr, w10, w11, bb0, bb1, w20, w21, bb2);
    out4[q1] = mlp4(a1, xa1.x, xa1.w, xb1.z, xc1.y,
                    wl, wr, w10, w11, bb0, bb1, w20, w21, bb2);
}

// ---------------------------------------------------------------------------
// Launch
// Inputs (metadata order): x[N,1] f32, edge_index[2,E] int32 (downcast from
// int64), W_l[1,1], W_r[1,1], W1[2,1], b1[2], W2[1,2], b2[1]
// Output: float[N/3]; out_size = 1,000,000 (divisible by 8).
// ---------------------------------------------------------------------------
extern "C" void kernel_launch(void* const* d_in, const int* in_sizes, int n_in,
                              void* d_out, int out_size) {
    const float* x  = (const float*)d_in[0];
    const int* edge_index = (const int*)d_in[1];
    const float* Wl = (const float*)d_in[2];
    const float* Wr = (const float*)d_in[3];
    const float* W1 = (const float*)d_in[4];
    const float* b1 = (const float*)d_in[5];
    const float* W2 = (const float*)d_in[6];
    const float* b2 = (const float*)d_in[7];
    float* out = (float*)d_out;

    int nedges = in_sizes[1] / 2;   // E (edge_index has 2*E elements)
    int m = out_size;               // N/3 output nodes
    int m8 = m / 8;

    const int* src = edge_index;
    const int* dst = edge_index + nedges;

    // 1) scatter: one thread per 8 edges, TPB=256 (best measured)
    int noct = nedges >> 3;
    int blocks = (noct + 255) / 256;
    scatter_kernel<<<blocks, 256>>>(src, dst, x, nedges);

    // 2) finalize: one thread per 8 outputs, TPB=128 for wave balance
    finalize_kernel<<<(m8 + 127) / 128, 128>>>(x, Wl, Wr, W1, b1, W2, b2, out, m8);
}